// round 15
// baseline (speedup 1.0000x reference)
#include <cuda_runtime.h>
#include <cuda_bf16.h>
#include <math.h>
#include <stdint.h>

// Problem constants
#define B_   32
#define N_   4096
#define D_   256
#define S_   16
#define K_   8
#define H_   128
#define LN_EPS 1e-5f
#define EPS_ 1e-8f
#define SCALE_ 0.25f

#define ML_GRID 512          // 32 batches x 16 groups of 256 n
#define ML_NT 256            // n per block
#define ML_THREADS 256
#define KV_PITCH 36

// ---------------- device scratch ----------------
__device__ __align__(16) float g_kv[(long long)B_ * N_ * 32];  // [b][n][k0..15|v0..15]
__device__ float g_num3[3 * B_ * K_ * S_];      // per-iteration accumulators
__device__ float g_den3[3 * B_ * K_];
__device__ unsigned g_bar;

__device__ __forceinline__ uint32_t smem_to_u32(const void* smem_ptr) {
    uint32_t addr;
    asm("{ .reg .u64 tmp; cvta.to.shared.u64 tmp, %1; cvt.u32.u64 %0, tmp; }"
        : "=r"(addr) : "l"(smem_ptr));
    return addr;
}

// ---------------- lnproj via mma.sync bf16 (512 threads; self-contained prep) ----------------
// Block: 512 threads, 128 x-rows, N=32 w-cols, K=256.
// C[m=w-col][n=x-row] = w[m][k] * x[n][k]; warp owns 8 x-rows, all 32 cols.
// smem: xh [128][528] @0, xl @67584, wh [32][528] @135168, wl @152064,
//       mu @168960, rs @169472, c1 @169984, c2 @170112; total 170240
#define XP_BYTES 528
#define XH_OFF 0
#define XL_OFF 67584
#define WH_OFF 135168
#define WL_OFF 152064
#define MU_OFF 168960
#define RS_OFF 169472
#define C1_OFF 169984
#define C2_OFF 170112
#define LM_SMEM_BYTES 170240

__device__ __forceinline__ void ldsm_x4(uint32_t* f, uint32_t addr) {
    asm volatile("ldmatrix.sync.aligned.m8n8.x4.shared.b16 {%0,%1,%2,%3}, [%4];"
                 : "=r"(f[0]), "=r"(f[1]), "=r"(f[2]), "=r"(f[3]) : "r"(addr));
}
__device__ __forceinline__ void ldsm_x2(uint32_t* f, uint32_t addr) {
    asm volatile("ldmatrix.sync.aligned.m8n8.x2.shared.b16 {%0,%1}, [%2];"
                 : "=r"(f[0]), "=r"(f[1]) : "r"(addr));
}
__device__ __forceinline__ void mma_bf16(float* c, const uint32_t* a, const uint32_t* b) {
    asm volatile(
        "mma.sync.aligned.m16n8k16.row.col.f32.bf16.bf16.f32 "
        "{%0,%1,%2,%3}, {%4,%5,%6,%7}, {%8,%9}, {%0,%1,%2,%3};"
        : "+f"(c[0]), "+f"(c[1]), "+f"(c[2]), "+f"(c[3])
        : "r"(a[0]), "r"(a[1]), "r"(a[2]), "r"(a[3]), "r"(b[0]), "r"(b[1]));
}

__global__ void __launch_bounds__(512) lnproj_mma_kernel(
    const float* __restrict__ in,
    const float* __restrict__ wk, const float* __restrict__ wv,
    const float* __restrict__ ln_w, const float* __restrict__ ln_b) {
    extern __shared__ char smem[];
    const uint32_t sb = smem_to_u32(smem);
    const int t = threadIdx.x;
    const int wid = t >> 5;            // 0..15
    const int lane = t & 31;
    const long long row0 = (long long)blockIdx.x * 128;

    // block 0: zero accumulators + reset grid barrier (stream-ordered before mainloop)
    // NOTE: 512 threads — ALL zero loops must stride, not predicate (R14 bug: g_den3[512..767]
    // was never cleared, accumulating across graph replays).
    if (blockIdx.x == 0) {
        for (int i = t; i < 3 * B_ * K_ * S_; i += 512) g_num3[i] = 0.f;
        for (int i = t; i < 3 * B_ * K_; i += 512) g_den3[i] = 0.f;
        if (t == 0) g_bar = 0u;
    }

    // per-block prep: bf16-split w-tiles into smem (8192 weights, 16/thread)
    for (int i = t; i < 8192; i += 512) {
        int n = i >> 8, kel = i & 255;
        float w = ((n < 16) ? __ldg(wk + n * D_ + kel) : __ldg(wv + (n - 16) * D_ + kel)) *
                  __ldg(ln_w + kel);
        __nv_bfloat16 h = __float2bfloat16(w);
        __nv_bfloat16 l = __float2bfloat16(w - __bfloat162float(h));
        *(__nv_bfloat16*)(smem + WH_OFF + n * XP_BYTES + kel * 2) = h;
        *(__nv_bfloat16*)(smem + WL_OFF + n * XP_BYTES + kel * 2) = l;
    }
    // per-block prep: c1/c2 — col = wid*2 + (lane>>4); 16 lanes x 16 elements each
    {
        int c = wid * 2 + (lane >> 4);
        int l16 = lane & 15;
        const float* wr = (c < 16) ? &wk[c * D_] : &wv[(c - 16) * D_];
        float c1 = 0.f, c2 = 0.f;
#pragma unroll
        for (int j = 0; j < 16; j++) {
            int d = l16 + j * 16;
            float wv_ = __ldg(wr + d);
            c1 = fmaf(wv_, __ldg(ln_w + d), c1);
            c2 = fmaf(wv_, __ldg(ln_b + d), c2);
        }
#pragma unroll
        for (int o = 1; o <= 8; o <<= 1) {
            c1 += __shfl_xor_sync(0xffffffffu, c1, o);
            c2 += __shfl_xor_sync(0xffffffffu, c2, o);
        }
        if (l16 == 0) {
            ((float*)(smem + C1_OFF))[c] = c1;
            ((float*)(smem + C2_OFF))[c] = c2;
        }
    }

    // stage x rows (hi+lo bf16) + fp32 LN stats (proven pattern; warps 0-7 only)
    if (t < 256) {
        const int r = t >> 1, half = t & 1;
        const float4* src = (const float4*)(in + (row0 + r) * D_ + half * 128);
        uint32_t* dh = (uint32_t*)(smem + XH_OFF + r * XP_BYTES + half * 256);
        uint32_t* dl = (uint32_t*)(smem + XL_OFF + r * XP_BYTES + half * 256);
        float sum = 0.f, ssq = 0.f;
#pragma unroll 8
        for (int j = 0; j < 32; j++) {
            float4 v = src[j];
            sum += (v.x + v.y) + (v.z + v.w);
            ssq = fmaf(v.x, v.x, ssq);
            ssq = fmaf(v.y, v.y, ssq);
            ssq = fmaf(v.z, v.z, ssq);
            ssq = fmaf(v.w, v.w, ssq);
            __nv_bfloat162 h0 = __floats2bfloat162_rn(v.x, v.y);
            __nv_bfloat162 h1 = __floats2bfloat162_rn(v.z, v.w);
            float2 f0 = __bfloat1622float2(h0);
            float2 f1 = __bfloat1622float2(h1);
            __nv_bfloat162 l0 = __floats2bfloat162_rn(v.x - f0.x, v.y - f0.y);
            __nv_bfloat162 l1 = __floats2bfloat162_rn(v.z - f1.x, v.w - f1.y);
            dh[2 * j] = *(uint32_t*)&h0;
            dh[2 * j + 1] = *(uint32_t*)&h1;
            dl[2 * j] = *(uint32_t*)&l0;
            dl[2 * j + 1] = *(uint32_t*)&l1;
        }
        sum += __shfl_xor_sync(0xffffffffu, sum, 1);
        ssq += __shfl_xor_sync(0xffffffffu, ssq, 1);
        if (half == 0) {
            float mu = sum * (1.f / 256.f);
            float var = ssq * (1.f / 256.f) - mu * mu;
            ((float*)(smem + MU_OFF))[r] = mu;
            ((float*)(smem + RS_OFF))[r] = rsqrtf(var + LN_EPS);
        }
    }
    __syncthreads();

    // MMA mainloop: warp owns x-rows [wid*8, wid*8+8), all 32 w-cols
    float acc[2][4];
#pragma unroll
    for (int mt = 0; mt < 2; mt++)
#pragma unroll
        for (int r = 0; r < 4; r++) acc[mt][r] = 0.f;

    const int n0 = wid * 8;
    const int am = lane & 15;               // A row within 16-row tile
    const int ak = (lane >> 4) << 3;        // A k-offset (0 or 8)
    const int bi = lane & 15;               // B lane pattern
    const int bn = bi & 7;                  // B row within 8-row tile
    const int bk = ((bi >> 3) & 1) << 3;    // B k-offset (0 or 8)

#pragma unroll 4
    for (int ks = 0; ks < 16; ks++) {
        const int k0 = ks * 16;
        uint32_t ah[2][4], al[2][4], bh[2], bl[2];
#pragma unroll
        for (int mt = 0; mt < 2; mt++) {
            uint32_t ro = (uint32_t)((mt * 16 + am) * XP_BYTES + (k0 + ak) * 2);
            ldsm_x4(ah[mt], sb + WH_OFF + ro);
            ldsm_x4(al[mt], sb + WL_OFF + ro);
        }
        {
            uint32_t ro = (uint32_t)((n0 + bn) * XP_BYTES + (k0 + bk) * 2);
            ldsm_x2(bh, sb + XH_OFF + ro);
            ldsm_x2(bl, sb + XL_OFF + ro);
        }
#pragma unroll
        for (int mt = 0; mt < 2; mt++) {
            mma_bf16(acc[mt], ah[mt], bh);
            mma_bf16(acc[mt], ah[mt], bl);
            mma_bf16(acc[mt], al[mt], bh);
        }
    }

    // epilogue: C[m=col][n=x-row]; apply LN correction in fp32, write g_kv
    const float* mup = (const float*)(smem + MU_OFF);
    const float* rsp = (const float*)(smem + RS_OFF);
    const float* c1p = (const float*)(smem + C1_OFF);
    const float* c2p = (const float*)(smem + C2_OFF);
#pragma unroll
    for (int mt = 0; mt < 2; mt++)
#pragma unroll
        for (int r = 0; r < 4; r++) {
            int col = mt * 16 + (lane >> 2) + ((r >> 1) << 3);
            int xrow = n0 + ((lane & 3) << 1) + (r & 1);
            float v = acc[mt][r];
            float o = fmaf(rsp[xrow], v - mup[xrow] * c1p[col], c2p[col]);
            g_kv[(row0 + xrow) * 32 + col] = o;
        }
}

// ---------------- persistent mainloop (R13-pass verbatim) ----------------
#define ML_SMEM_FLOATS 13728

__device__ __forceinline__ void grid_barrier(unsigned target) {
    __syncthreads();
    if (threadIdx.x == 0) {
        __threadfence();
        atomicAdd(&g_bar, 1u);
        while (*((volatile unsigned*)&g_bar) < target) {
            __nanosleep(64);
        }
        __threadfence();
    }
    __syncthreads();
}

__global__ void __launch_bounds__(ML_THREADS, 4) mainloop_kernel(
    const float* __restrict__ init_slots,
    const float* __restrict__ ln_s_w, const float* __restrict__ ln_s_b,
    const float* __restrict__ wq,
    const float* __restrict__ w_ih, const float* __restrict__ w_hh,
    const float* __restrict__ b_ih, const float* __restrict__ b_hh,
    const float* __restrict__ ln_m_w, const float* __restrict__ ln_m_b,
    const float* __restrict__ w1, const float* __restrict__ b1,
    const float* __restrict__ w2, const float* __restrict__ b2,
    float* __restrict__ out_slots, float* __restrict__ out_attn) {
    extern __shared__ float smf[];
    float* kvs = smf;
    float* slb = smf + 9216;
    float* qlo = smf + 9344;
    float* S1 = smf + 9472;
    float* S2 = smf + 11648;

    const int bx = blockIdx.x;
    const int b = bx >> 4;
    const int grp = bx & 15;
    const int n0 = grp * ML_NT;
    const int t = threadIdx.x;          // 0..255
    const int k = t & 7;
    const int g = t >> 3;               // 0..31
    const int lane = t & 31;
    const int warp = t >> 5;            // 0..7

    {
        const float4* src = (const float4*)(g_kv + ((long long)b * N_ + n0) * 32);
#pragma unroll
        for (int i = 0; i < 8; i++) {
            int idx = t + i * ML_THREADS;
            int r = idx >> 3, f = idx & 7;
            *(float4*)&kvs[r * KV_PITCH + 4 * f] = src[idx];
        }
    }
    if (t < 128) slb[t] = init_slots[b * 128 + t];
    __syncthreads();

    if (t < K_) {
        float x[S_];
        float s = 0.f;
#pragma unroll
        for (int j = 0; j < S_; j++) {
            x[j] = slb[t * S_ + j];
            s += x[j];
        }
        float mu = s * (1.f / 16.f);
        float ss = 0.f;
#pragma unroll
        for (int j = 0; j < S_; j++) {
            float d = x[j] - mu;
            ss = fmaf(d, d, ss);
        }
        float rs = rsqrtf(ss * (1.f / 16.f) + LN_EPS);
        float y[S_];
#pragma unroll
        for (int j = 0; j < S_; j++) y[j] = (x[j] - mu) * rs * __ldg(ln_s_w + j) + __ldg(ln_s_b + j);
#pragma unroll
        for (int tt = 0; tt < S_; tt++) {
            float q = 0.f;
#pragma unroll
            for (int j = 0; j < S_; j++) q = fmaf(y[j], __ldg(wq + tt * S_ + j), q);
            qlo[t * S_ + tt] = q;
        }
    }
    __syncthreads();

    for (int it = 0; it < 3; it++) {
        float qr[S_];
#pragma unroll
        for (int s = 0; s < S_; s++) qr[s] = qlo[k * S_ + s];
        float num[S_];
#pragma unroll
        for (int s = 0; s < S_; s++) num[s] = 0.f;
        float den = 0.f;

#pragma unroll 2
        for (int j = 0; j < ML_NT / 32; j++) {
            int nl = g + 32 * j;
            const float* kn = &kvs[nl * KV_PITCH];
            float logit = 0.f;
#pragma unroll
            for (int s = 0; s < S_; s++) logit = fmaf(qr[s], kn[s], logit);
            logit *= SCALE_;
            float m = logit;
            m = fmaxf(m, __shfl_xor_sync(0xffffffffu, m, 1));
            m = fmaxf(m, __shfl_xor_sync(0xffffffffu, m, 2));
            m = fmaxf(m, __shfl_xor_sync(0xffffffffu, m, 4));
            float e = __expf(logit - m);
            float sum = e;
            sum += __shfl_xor_sync(0xffffffffu, sum, 1);
            sum += __shfl_xor_sync(0xffffffffu, sum, 2);
            sum += __shfl_xor_sync(0xffffffffu, sum, 4);
            float a = e / sum + EPS_;
            if (it == 2) S2[k * (ML_NT + 4) + nl] = a;
            den += a;
            const float* vn = kn + 16;
#pragma unroll
            for (int s = 0; s < S_; s++) num[s] = fmaf(a, vn[s], num[s]);
        }

#pragma unroll
        for (int o = 8; o <= 16; o <<= 1) {
#pragma unroll
            for (int s = 0; s < S_; s++) num[s] += __shfl_xor_sync(0xffffffffu, num[s], o);
            den += __shfl_xor_sync(0xffffffffu, den, o);
        }
        __syncthreads();
        if (lane < 8) {
            float* rp = &S1[(warp * 8 + lane) * 17];
#pragma unroll
            for (int s = 0; s < S_; s++) rp[s] = num[s];
            rp[16] = den;
        }
        __syncthreads();
        if (t < 136) {
            int k2 = t / 17, s2 = t % 17;
            float v = 0.f;
#pragma unroll
            for (int w = 0; w < 8; w++) v += S1[(w * 8 + k2) * 17 + s2];
            if (s2 < 16)
                atomicAdd(&g_num3[it * 4096 + b * 128 + k2 * 16 + s2], v);
            else
                atomicAdd(&g_den3[it * 256 + b * K_ + k2], v);
        }

        grid_barrier((unsigned)ML_GRID * (unsigned)(it + 1));

        if (t < 128) {
            float u_num = __ldcg(&g_num3[it * 4096 + b * 128 + t]);
            float u_den = __ldcg(&g_den3[it * 256 + b * K_ + (t >> 4)]);
            S1[t] = u_num / u_den;
        }

        if (it == 2) {
            if (t < K_) qlo[t] = 1.0f / __ldcg(&g_den3[it * 256 + b * K_ + t]);
            __syncthreads();
#pragma unroll 4
            for (int i = t; i < K_ * ML_NT; i += ML_THREADS) {
                int kk = i >> 8, nn = i & (ML_NT - 1);
                out_attn[((long long)(b * K_ + kk)) * N_ + n0 + nn] =
                    S2[kk * (ML_NT + 4) + nn] * qlo[kk];
            }
        }
        __syncthreads();

        for (int i = t; i < 768; i += ML_THREADS) {
            S2[i] = __ldg(w_ih + i);
            S2[768 + i] = __ldg(w_hh + i);
        }
        __syncthreads();
        for (int idx = t; idx < 384; idx += ML_THREADS) {
            int kk = idx / 48, j = idx % 48;
            float gi = __ldg(b_ih + j), gh = __ldg(b_hh + j);
#pragma unroll
            for (int s = 0; s < S_; s++) {
                gi = fmaf(S1[kk * S_ + s], S2[j * S_ + s], gi);
                gh = fmaf(slb[kk * S_ + s], S2[768 + j * S_ + s], gh);
            }
            S1[384 + idx] = gi;
            S1[768 + idx] = gh;
        }
        __syncthreads();
        if (t < 128) {
            int kk = t >> 4, s = t & 15;
            float ir = S1[384 + kk * 48 + s], hr = S1[768 + kk * 48 + s];
            float iz = S1[384 + kk * 48 + 16 + s], hz = S1[768 + kk * 48 + 16 + s];
            float inn = S1[384 + kk * 48 + 32 + s], hn = S1[768 + kk * 48 + 32 + s];
            float r = 1.f / (1.f + __expf(-(ir + hr)));
            float z = 1.f / (1.f + __expf(-(iz + hz)));
            float n = tanhf(inn + r * hn);
            float h = (1.f - z) * n + z * slb[t];
            S1[128 + t] = h;
            float s1 = h, s2 = h * h;
#pragma unroll
            for (int o = 1; o <= 8; o <<= 1) {
                s1 += __shfl_xor_sync(0xffffffffu, s1, o);
                s2 += __shfl_xor_sync(0xffffffffu, s2, o);
            }
            float mu = s1 * (1.f / 16.f);
            float var = s2 * (1.f / 16.f) - mu * mu;
            float rs = rsqrtf(var + LN_EPS);
            S1[256 + t] = (h - mu) * rs * __ldg(ln_m_w + s) + __ldg(ln_m_b + s);
        }
        __syncthreads();
        for (int i = t; i < H_ * S_; i += ML_THREADS) S2[i] = __ldg(w1 + i);
        __syncthreads();
        for (int idx = t; idx < K_ * H_; idx += ML_THREADS) {
            int kk = idx >> 7, hh = idx & 127;
            float acc = __ldg(b1 + hh);
#pragma unroll
            for (int s = 0; s < S_; s++) acc = fmaf(S1[256 + kk * S_ + s], S2[hh * S_ + s], acc);
            S1[1152 + idx] = fmaxf(acc, 0.f);
        }
        __syncthreads();
        for (int i = t; i < S_ * H_; i += ML_THREADS) S2[i] = __ldg(w2 + i);
        __syncthreads();
        float res = 0.f;
        if (t < 128) {
            int kk = t >> 4, s = t & 15;
            float acc = __ldg(b2 + s);
#pragma unroll 8
            for (int h = 0; h < H_; h++) acc = fmaf(S1[1152 + kk * H_ + h], S2[s * H_ + h], acc);
            res = S1[128 + t] + acc;
        }

        if (it == 2) {
            if (grp == 0 && t < 128) out_slots[b * 128 + t] = res;
        } else {
            __syncthreads();
            if (t < 128) slb[t] = res;
            __syncthreads();
            if (t < K_) {
                float x[S_];
                float s = 0.f;
#pragma unroll
                for (int j = 0; j < S_; j++) {
                    x[j] = slb[t * S_ + j];
                    s += x[j];
                }
                float mu = s * (1.f / 16.f);
                float ss = 0.f;
#pragma unroll
                for (int j = 0; j < S_; j++) {
                    float d = x[j] - mu;
                    ss = fmaf(d, d, ss);
                }
                float rs = rsqrtf(ss * (1.f / 16.f) + LN_EPS);
                float y[S_];
#pragma unroll
                for (int j = 0; j < S_; j++)
                    y[j] = (x[j] - mu) * rs * __ldg(ln_s_w + j) + __ldg(ln_s_b + j);
#pragma unroll
                for (int tt = 0; tt < S_; tt++) {
                    float q = 0.f;
#pragma unroll
                    for (int j = 0; j < S_; j++) q = fmaf(y[j], __ldg(wq + tt * S_ + j), q);
                    qlo[t * S_ + tt] = q;
                }
            }
            __syncthreads();
        }
    }
}

// ---------------- launch: 2 graph nodes ----------------
extern "C" void kernel_launch(void* const* d_in, const int* in_sizes, int n_in,
                              void* d_out, int out_size) {
    const float* inputs = (const float*)d_in[0];
    const float* init_slots = (const float*)d_in[1];
    const float* ln_in_w = (const float*)d_in[2];
    const float* ln_in_b = (const float*)d_in[3];
    const float* ln_s_w = (const float*)d_in[4];
    const float* ln_s_b = (const float*)d_in[5];
    const float* ln_m_w = (const float*)d_in[6];
    const float* ln_m_b = (const float*)d_in[7];
    const float* wq = (const float*)d_in[8];
    const float* wk = (const float*)d_in[9];
    const float* wv = (const float*)d_in[10];
    const float* w_ih = (const float*)d_in[11];
    const float* w_hh = (const float*)d_in[12];
    const float* b_ih = (const float*)d_in[13];
    const float* b_hh = (const float*)d_in[14];
    const float* mlp_w1 = (const float*)d_in[15];
    const float* mlp_b1 = (const float*)d_in[16];
    const float* mlp_w2 = (const float*)d_in[17];
    const float* mlp_b2 = (const float*)d_in[18];

    float* out_slots = (float*)d_out;
    float* out_attn = out_slots + B_ * K_ * S_;

    cudaFuncSetAttribute(lnproj_mma_kernel, cudaFuncAttributeMaxDynamicSharedMemorySize, LM_SMEM_BYTES);
    const int ml_smem = ML_SMEM_FLOATS * sizeof(float);
    cudaFuncSetAttribute(mainloop_kernel, cudaFuncAttributeMaxDynamicSharedMemorySize, ml_smem);

    lnproj_mma_kernel<<<(B_ * N_) / 128, 512, LM_SMEM_BYTES>>>(inputs, wk, wv, ln_in_w, ln_in_b);
    mainloop_kernel<<<ML_GRID, ML_THREADS, ml_smem>>>(
        init_slots, ln_s_w, ln_s_b, wq, w_ih, w_hh, b_ih, b_hh,
        ln_m_w, ln_m_b, mlp_w1, mlp_b1, mlp_w2, mlp_b2, out_slots, out_attn);
}

// round 16
// speedup vs baseline: 1.0072x; 1.0072x over previous
#include <cuda_runtime.h>
#include <cuda_bf16.h>
#include <math.h>
#include <stdint.h>

// Problem constants
#define B_   32
#define N_   4096
#define D_   256
#define S_   16
#define K_   8
#define H_   128
#define LN_EPS 1e-5f
#define EPS_ 1e-8f
#define SCALE_ 0.25f

#define ML_GRID 512          // 32 batches x 16 groups of 256 n
#define ML_NT 256            // n per block
#define ML_THREADS 256
#define KV_PITCH 36

// ---------------- device scratch ----------------
__device__ float g_c1[32];
__device__ float g_c2[32];
__device__ __align__(16) float g_kv[(long long)B_ * N_ * 32];  // [b][n][k0..15|v0..15]
__device__ __align__(16) unsigned short g_wbh[32 * 256];       // bf16 hi w  [n][k] row-major
__device__ __align__(16) unsigned short g_wbl[32 * 256];       // bf16 lo w
__device__ float g_num3[3 * B_ * K_ * S_];      // per-iteration accumulators
__device__ float g_den3[3 * B_ * K_];
__device__ unsigned g_bar;

__device__ __forceinline__ uint32_t smem_to_u32(const void* smem_ptr) {
    uint32_t addr;
    asm("{ .reg .u64 tmp; cvta.to.shared.u64 tmp, %1; cvt.u32.u64 %0, tmp; }"
        : "=r"(addr) : "l"(smem_ptr));
    return addr;
}

// ---------------- prep (R13-pass verbatim) ----------------
__global__ void __launch_bounds__(1024) prep_kernel(
    const float* __restrict__ wk, const float* __restrict__ wv,
    const float* __restrict__ ln_w, const float* __restrict__ ln_b) {
    const int t = threadIdx.x;  // 1024
#pragma unroll
    for (int i = 0; i < 8; i++) {
        int idx = t + i * 1024;
        int n = idx >> 8, kel = idx & 255;
        float w = ((n < 16) ? wk[n * D_ + kel] : wv[(n - 16) * D_ + kel]) * ln_w[kel];
        __nv_bfloat16 h = __float2bfloat16(w);
        __nv_bfloat16 l = __float2bfloat16(w - __bfloat162float(h));
        g_wbh[idx] = *(unsigned short*)&h;
        g_wbl[idx] = *(unsigned short*)&l;
    }
    {
        int w = t >> 5, l = t & 31;
        const float* wr = (w < 16) ? &wk[w * D_] : &wv[(w - 16) * D_];
        float c1 = 0.f, c2 = 0.f;
#pragma unroll
        for (int j = 0; j < 8; j++) {
            int d = l + j * 32;
            float wv_ = wr[d];
            c1 = fmaf(wv_, ln_w[d], c1);
            c2 = fmaf(wv_, ln_b[d], c2);
        }
#pragma unroll
        for (int o = 16; o >= 1; o >>= 1) {
            c1 += __shfl_xor_sync(0xffffffffu, c1, o);
            c2 += __shfl_xor_sync(0xffffffffu, c2, o);
        }
        if (l == 0) {
            g_c1[w] = c1;
            g_c2[w] = c2;
        }
    }
#pragma unroll
    for (int i = 0; i < 12; i++) g_num3[t + i * 1024] = 0.f;
    if (t < 768) g_den3[t] = 0.f;
    if (t == 0) g_bar = 0u;
}

// ---------------- lnproj via mma.sync bf16 (R13-pass verbatim; 512 threads) ----------------
#define XP_BYTES 528
#define XH_OFF 0
#define XL_OFF 67584
#define WH_OFF 135168
#define WL_OFF 152064
#define MU_OFF 168960
#define RS_OFF 169472
#define LM_SMEM_BYTES 169984

__device__ __forceinline__ void ldsm_x4(uint32_t* f, uint32_t addr) {
    asm volatile("ldmatrix.sync.aligned.m8n8.x4.shared.b16 {%0,%1,%2,%3}, [%4];"
                 : "=r"(f[0]), "=r"(f[1]), "=r"(f[2]), "=r"(f[3]) : "r"(addr));
}
__device__ __forceinline__ void ldsm_x2(uint32_t* f, uint32_t addr) {
    asm volatile("ldmatrix.sync.aligned.m8n8.x2.shared.b16 {%0,%1}, [%2];"
                 : "=r"(f[0]), "=r"(f[1]) : "r"(addr));
}
__device__ __forceinline__ void mma_bf16(float* c, const uint32_t* a, const uint32_t* b) {
    asm volatile(
        "mma.sync.aligned.m16n8k16.row.col.f32.bf16.bf16.f32 "
        "{%0,%1,%2,%3}, {%4,%5,%6,%7}, {%8,%9}, {%0,%1,%2,%3};"
        : "+f"(c[0]), "+f"(c[1]), "+f"(c[2]), "+f"(c[3])
        : "r"(a[0]), "r"(a[1]), "r"(a[2]), "r"(a[3]), "r"(b[0]), "r"(b[1]));
}

__global__ void __launch_bounds__(512) lnproj_mma_kernel(const float* __restrict__ in) {
    extern __shared__ char smem[];
    const uint32_t sb = smem_to_u32(smem);
    const int t = threadIdx.x;
    const int wid = t >> 5;            // 0..15
    const int lane = t & 31;
    const long long row0 = (long long)blockIdx.x * 128;

    for (int i = t; i < 4096; i += 512) {
        int n = i >> 7;
        int kk = (i & 127) * 2;
        uint32_t vh = ((const uint32_t*)g_wbh)[i];
        uint32_t vl = ((const uint32_t*)g_wbl)[i];
        *(uint32_t*)(smem + WH_OFF + n * XP_BYTES + kk * 2) = vh;
        *(uint32_t*)(smem + WL_OFF + n * XP_BYTES + kk * 2) = vl;
    }

    if (t < 256) {
        const int r = t >> 1, half = t & 1;
        const float4* src = (const float4*)(in + (row0 + r) * D_ + half * 128);
        uint32_t* dh = (uint32_t*)(smem + XH_OFF + r * XP_BYTES + half * 256);
        uint32_t* dl = (uint32_t*)(smem + XL_OFF + r * XP_BYTES + half * 256);
        float sum = 0.f, ssq = 0.f;
#pragma unroll 8
        for (int j = 0; j < 32; j++) {
            float4 v = src[j];
            sum += (v.x + v.y) + (v.z + v.w);
            ssq = fmaf(v.x, v.x, ssq);
            ssq = fmaf(v.y, v.y, ssq);
            ssq = fmaf(v.z, v.z, ssq);
            ssq = fmaf(v.w, v.w, ssq);
            __nv_bfloat162 h0 = __floats2bfloat162_rn(v.x, v.y);
            __nv_bfloat162 h1 = __floats2bfloat162_rn(v.z, v.w);
            float2 f0 = __bfloat1622float2(h0);
            float2 f1 = __bfloat1622float2(h1);
            __nv_bfloat162 l0 = __floats2bfloat162_rn(v.x - f0.x, v.y - f0.y);
            __nv_bfloat162 l1 = __floats2bfloat162_rn(v.z - f1.x, v.w - f1.y);
            dh[2 * j] = *(uint32_t*)&h0;
            dh[2 * j + 1] = *(uint32_t*)&h1;
            dl[2 * j] = *(uint32_t*)&l0;
            dl[2 * j + 1] = *(uint32_t*)&l1;
        }
        sum += __shfl_xor_sync(0xffffffffu, sum, 1);
        ssq += __shfl_xor_sync(0xffffffffu, ssq, 1);
        if (half == 0) {
            float mu = sum * (1.f / 256.f);
            float var = ssq * (1.f / 256.f) - mu * mu;
            ((float*)(smem + MU_OFF))[r] = mu;
            ((float*)(smem + RS_OFF))[r] = rsqrtf(var + LN_EPS);
        }
    }
    __syncthreads();

    float acc[2][4];
#pragma unroll
    for (int mt = 0; mt < 2; mt++)
#pragma unroll
        for (int r = 0; r < 4; r++) acc[mt][r] = 0.f;

    const int n0 = wid * 8;
    const int am = lane & 15;
    const int ak = (lane >> 4) << 3;
    const int bi = lane & 15;
    const int bn = bi & 7;
    const int bk = ((bi >> 3) & 1) << 3;

#pragma unroll 4
    for (int ks = 0; ks < 16; ks++) {
        const int k0 = ks * 16;
        uint32_t ah[2][4], al[2][4], bh[2], bl[2];
#pragma unroll
        for (int mt = 0; mt < 2; mt++) {
            uint32_t ro = (uint32_t)((mt * 16 + am) * XP_BYTES + (k0 + ak) * 2);
            ldsm_x4(ah[mt], sb + WH_OFF + ro);
            ldsm_x4(al[mt], sb + WL_OFF + ro);
        }
        {
            uint32_t ro = (uint32_t)((n0 + bn) * XP_BYTES + (k0 + bk) * 2);
            ldsm_x2(bh, sb + XH_OFF + ro);
            ldsm_x2(bl, sb + XL_OFF + ro);
        }
#pragma unroll
        for (int mt = 0; mt < 2; mt++) {
            mma_bf16(acc[mt], ah[mt], bh);
            mma_bf16(acc[mt], ah[mt], bl);
            mma_bf16(acc[mt], al[mt], bh);
        }
    }

    const float* mup = (const float*)(smem + MU_OFF);
    const float* rsp = (const float*)(smem + RS_OFF);
#pragma unroll
    for (int mt = 0; mt < 2; mt++)
#pragma unroll
        for (int r = 0; r < 4; r++) {
            int col = mt * 16 + (lane >> 2) + ((r >> 1) << 3);
            int xrow = n0 + ((lane & 3) << 1) + (r & 1);
            float v = acc[mt][r];
            float o = fmaf(rsp[xrow], v - mup[xrow] * g_c1[col], g_c2[col]);
            g_kv[(row0 + xrow) * 32 + col] = o;
        }
}

// ---------------- persistent mainloop: shuffle-free attention ----------------
// smem (floats): kvs [0:9216), slb [9216:9344), qlo [9344:9472),
//                S1 [9472:11648), S2/a_s [11648:13952)  -> total 13952 (55.8 KB)
#define ML_SMEM_FLOATS 13952

__device__ __forceinline__ void grid_barrier(unsigned target) {
    __syncthreads();
    if (threadIdx.x == 0) {
        __threadfence();
        atomicAdd(&g_bar, 1u);
        while (*((volatile unsigned*)&g_bar) < target) {
            __nanosleep(64);
        }
        __threadfence();
    }
    __syncthreads();
}

__global__ void __launch_bounds__(ML_THREADS, 4) mainloop_kernel(
    const float* __restrict__ init_slots,
    const float* __restrict__ ln_s_w, const float* __restrict__ ln_s_b,
    const float* __restrict__ wq,
    const float* __restrict__ w_ih, const float* __restrict__ w_hh,
    const float* __restrict__ b_ih, const float* __restrict__ b_hh,
    const float* __restrict__ ln_m_w, const float* __restrict__ ln_m_b,
    const float* __restrict__ w1, const float* __restrict__ b1,
    const float* __restrict__ w2, const float* __restrict__ b2,
    float* __restrict__ out_slots, float* __restrict__ out_attn) {
    extern __shared__ float smf[];
    float* kvs = smf;
    float* slb = smf + 9216;
    float* qlo = smf + 9344;
    float* S1 = smf + 9472;
    float* S2 = smf + 11648;   // a_s [256][9] = 2304 floats

    const int bx = blockIdx.x;
    const int b = bx >> 4;
    const int grp = bx & 15;
    const int n0 = grp * ML_NT;
    const int t = threadIdx.x;          // 0..255

    {
        const float4* src = (const float4*)(g_kv + ((long long)b * N_ + n0) * 32);
#pragma unroll
        for (int i = 0; i < 8; i++) {
            int idx = t + i * ML_THREADS;
            int r = idx >> 3, f = idx & 7;
            *(float4*)&kvs[r * KV_PITCH + 4 * f] = src[idx];
        }
    }
    kvs[t * KV_PITCH + 32] = 1.0f;      // ones column -> den in phase 2
    if (t < 128) slb[t] = init_slots[b * 128 + t];
    __syncthreads();

    if (t < K_) {
        float x[S_];
        float s = 0.f;
#pragma unroll
        for (int j = 0; j < S_; j++) {
            x[j] = slb[t * S_ + j];
            s += x[j];
        }
        float mu = s * (1.f / 16.f);
        float ss = 0.f;
#pragma unroll
        for (int j = 0; j < S_; j++) {
            float d = x[j] - mu;
            ss = fmaf(d, d, ss);
        }
        float rs = rsqrtf(ss * (1.f / 16.f) + LN_EPS);
        float y[S_];
#pragma unroll
        for (int j = 0; j < S_; j++) y[j] = (x[j] - mu) * rs * __ldg(ln_s_w + j) + __ldg(ln_s_b + j);
#pragma unroll
        for (int tt = 0; tt < S_; tt++) {
            float q = 0.f;
#pragma unroll
            for (int j = 0; j < S_; j++) q = fmaf(y[j], __ldg(wq + tt * S_ + j), q);
            qlo[t * S_ + tt] = q;
        }
    }
    __syncthreads();

    for (int it = 0; it < 3; it++) {
        // ---------- attn phase 1: thread t owns n = t; softmax in registers ----------
        {
            const float* kn = &kvs[t * KV_PITCH];
            float4 kr0 = *(const float4*)(kn + 0);
            float4 kr1 = *(const float4*)(kn + 4);
            float4 kr2 = *(const float4*)(kn + 8);
            float4 kr3 = *(const float4*)(kn + 12);

            float logit[K_];
#pragma unroll
            for (int k = 0; k < K_; k++) {
                float4 q0 = *(const float4*)&qlo[k * S_ + 0];
                float4 q1 = *(const float4*)&qlo[k * S_ + 4];
                float4 q2 = *(const float4*)&qlo[k * S_ + 8];
                float4 q3 = *(const float4*)&qlo[k * S_ + 12];
                float a = q0.x * kr0.x;
                a = fmaf(q0.y, kr0.y, a);
                a = fmaf(q0.z, kr0.z, a);
                a = fmaf(q0.w, kr0.w, a);
                a = fmaf(q1.x, kr1.x, a);
                a = fmaf(q1.y, kr1.y, a);
                a = fmaf(q1.z, kr1.z, a);
                a = fmaf(q1.w, kr1.w, a);
                a = fmaf(q2.x, kr2.x, a);
                a = fmaf(q2.y, kr2.y, a);
                a = fmaf(q2.z, kr2.z, a);
                a = fmaf(q2.w, kr2.w, a);
                a = fmaf(q3.x, kr3.x, a);
                a = fmaf(q3.y, kr3.y, a);
                a = fmaf(q3.z, kr3.z, a);
                a = fmaf(q3.w, kr3.w, a);
                logit[k] = a * SCALE_;
            }
            float m = logit[0];
#pragma unroll
            for (int k = 1; k < K_; k++) m = fmaxf(m, logit[k]);
            float e[K_];
            float sum = 0.f;
#pragma unroll
            for (int k = 0; k < K_; k++) {
                e[k] = __expf(logit[k] - m);
                sum += e[k];
            }
            float inv = __fdividef(1.f, sum);
#pragma unroll
            for (int k = 0; k < K_; k++) S2[t * 9 + k] = fmaf(e[k], inv, EPS_);
        }
        __syncthreads();

        // ---------- attn phase 2: num[k][s] (+den via ones col) over 256 n ----------
        if (t < 136) {
            int k2 = t / 17, c = 16 + t % 17;
            float a0 = 0.f, a1 = 0.f, a2 = 0.f, a3 = 0.f;
#pragma unroll 8
            for (int n = 0; n < ML_NT; n += 4) {
                a0 = fmaf(S2[n * 9 + k2], kvs[n * KV_PITCH + c], a0);
                a1 = fmaf(S2[(n + 1) * 9 + k2], kvs[(n + 1) * KV_PITCH + c], a1);
                a2 = fmaf(S2[(n + 2) * 9 + k2], kvs[(n + 2) * KV_PITCH + c], a2);
                a3 = fmaf(S2[(n + 3) * 9 + k2], kvs[(n + 3) * KV_PITCH + c], a3);
            }
            float acc = (a0 + a1) + (a2 + a3);
            if (c < 32)
                atomicAdd(&g_num3[it * 4096 + b * 128 + k2 * 16 + (c - 16)], acc);
            else
                atomicAdd(&g_den3[it * 256 + b * K_ + k2], acc);
        }

        grid_barrier((unsigned)ML_GRID * (unsigned)(it + 1));

        if (t < 128) {
            float u_num = __ldcg(&g_num3[it * 4096 + b * 128 + t]);
            float u_den = __ldcg(&g_den3[it * 256 + b * K_ + (t >> 4)]);
            S1[t] = u_num / u_den;
        }

        if (it == 2) {
            if (t < K_) qlo[t] = 1.0f / __ldcg(&g_den3[it * 256 + b * K_ + t]);
            __syncthreads();
#pragma unroll 4
            for (int i = t; i < K_ * ML_NT; i += ML_THREADS) {
                int kk = i >> 8, nn = i & (ML_NT - 1);
                out_attn[((long long)(b * K_ + kk)) * N_ + n0 + nn] =
                    S2[nn * 9 + kk] * qlo[kk];
            }
        }
        __syncthreads();

        // ---------- update phase (R13-pass verbatim) ----------
        for (int i = t; i < 768; i += ML_THREADS) {
            S2[i] = __ldg(w_ih + i);
            S2[768 + i] = __ldg(w_hh + i);
        }
        __syncthreads();
        for (int idx = t; idx < 384; idx += ML_THREADS) {
            int kk = idx / 48, j = idx % 48;
            float gi = __ldg(b_ih + j), gh = __ldg(b_hh + j);
#pragma unroll
            for (int s = 0; s < S_; s++) {
                gi = fmaf(S1[kk * S_ + s], S2[j * S_ + s], gi);
                gh = fmaf(slb[kk * S_ + s], S2[768 + j * S_ + s], gh);
            }
            S1[384 + idx] = gi;
            S1[768 + idx] = gh;
        }
        __syncthreads();
        if (t < 128) {
            int kk = t >> 4, s = t & 15;
            float ir = S1[384 + kk * 48 + s], hr = S1[768 + kk * 48 + s];
            float iz = S1[384 + kk * 48 + 16 + s], hz = S1[768 + kk * 48 + 16 + s];
            float inn = S1[384 + kk * 48 + 32 + s], hn = S1[768 + kk * 48 + 32 + s];
            float r = 1.f / (1.f + __expf(-(ir + hr)));
            float z = 1.f / (1.f + __expf(-(iz + hz)));
            float n = tanhf(inn + r * hn);
            float h = (1.f - z) * n + z * slb[t];
            S1[128 + t] = h;
            float s1 = h, s2 = h * h;
#pragma unroll
            for (int o = 1; o <= 8; o <<= 1) {
                s1 += __shfl_xor_sync(0xffffffffu, s1, o);
                s2 += __shfl_xor_sync(0xffffffffu, s2, o);
            }
            float mu = s1 * (1.f / 16.f);
            float var = s2 * (1.f / 16.f) - mu * mu;
            float rs = rsqrtf(var + LN_EPS);
            S1[256 + t] = (h - mu) * rs * __ldg(ln_m_w + s) + __ldg(ln_m_b + s);
        }
        __syncthreads();
        for (int i = t; i < H_ * S_; i += ML_THREADS) S2[i] = __ldg(w1 + i);
        __syncthreads();
        for (int idx = t; idx < K_ * H_; idx += ML_THREADS) {
            int kk = idx >> 7, hh = idx & 127;
            float acc = __ldg(b1 + hh);
#pragma unroll
            for (int s = 0; s < S_; s++) acc = fmaf(S1[256 + kk * S_ + s], S2[hh * S_ + s], acc);
            S1[1152 + idx] = fmaxf(acc, 0.f);
        }
        __syncthreads();
        for (int i = t; i < S_ * H_; i += ML_THREADS) S2[i] = __ldg(w2 + i);
        __syncthreads();
        float res = 0.f;
        if (t < 128) {
            int kk = t >> 4, s = t & 15;
            float acc = __ldg(b2 + s);
#pragma unroll 8
            for (int h = 0; h < H_; h++) acc = fmaf(S1[1152 + kk * H_ + h], S2[s * H_ + h], acc);
            res = S1[128 + t] + acc;
        }

        if (it == 2) {
            if (grp == 0 && t < 128) out_slots[b * 128 + t] = res;
        } else {
            __syncthreads();
            if (t < 128) slb[t] = res;
            __syncthreads();
            if (t < K_) {
                float x[S_];
                float s = 0.f;
#pragma unroll
                for (int j = 0; j < S_; j++) {
                    x[j] = slb[t * S_ + j];
                    s += x[j];
                }
                float mu = s * (1.f / 16.f);
                float ss = 0.f;
#pragma unroll
                for (int j = 0; j < S_; j++) {
                    float d = x[j] - mu;
                    ss = fmaf(d, d, ss);
                }
                float rs = rsqrtf(ss * (1.f / 16.f) + LN_EPS);
                float y[S_];
#pragma unroll
                for (int j = 0; j < S_; j++)
                    y[j] = (x[j] - mu) * rs * __ldg(ln_s_w + j) + __ldg(ln_s_b + j);
#pragma unroll
                for (int tt = 0; tt < S_; tt++) {
                    float q = 0.f;
#pragma unroll
                    for (int j = 0; j < S_; j++) q = fmaf(y[j], __ldg(wq + tt * S_ + j), q);
                    qlo[t * S_ + tt] = q;
                }
            }
            __syncthreads();
        }
    }
}

// ---------------- launch: 3 graph nodes ----------------
extern "C" void kernel_launch(void* const* d_in, const int* in_sizes, int n_in,
                              void* d_out, int out_size) {
    const float* inputs = (const float*)d_in[0];
    const float* init_slots = (const float*)d_in[1];
    const float* ln_in_w = (const float*)d_in[2];
    const float* ln_in_b = (const float*)d_in[3];
    const float* ln_s_w = (const float*)d_in[4];
    const float* ln_s_b = (const float*)d_in[5];
    const float* ln_m_w = (const float*)d_in[6];
    const float* ln_m_b = (const float*)d_in[7];
    const float* wq = (const float*)d_in[8];
    const float* wk = (const float*)d_in[9];
    const float* wv = (const float*)d_in[10];
    const float* w_ih = (const float*)d_in[11];
    const float* w_hh = (const float*)d_in[12];
    const float* b_ih = (const float*)d_in[13];
    const float* b_hh = (const float*)d_in[14];
    const float* mlp_w1 = (const float*)d_in[15];
    const float* mlp_b1 = (const float*)d_in[16];
    const float* mlp_w2 = (const float*)d_in[17];
    const float* mlp_b2 = (const float*)d_in[18];

    float* out_slots = (float*)d_out;
    float* out_attn = out_slots + B_ * K_ * S_;

    cudaFuncSetAttribute(lnproj_mma_kernel, cudaFuncAttributeMaxDynamicSharedMemorySize, LM_SMEM_BYTES);
    const int ml_smem = ML_SMEM_FLOATS * sizeof(float);
    cudaFuncSetAttribute(mainloop_kernel, cudaFuncAttributeMaxDynamicSharedMemorySize, ml_smem);

    prep_kernel<<<1, 1024>>>(wk, wv, ln_in_w, ln_in_b);
    lnproj_mma_kernel<<<(B_ * N_) / 128, 512, LM_SMEM_BYTES>>>(inputs);
    mainloop_kernel<<<ML_GRID, ML_THREADS, ml_smem>>>(
        init_slots, ln_s_w, ln_s_b, wq, w_ih, w_hh, b_ih, b_hh,
        ln_m_w, ln_m_b, mlp_w1, mlp_b1, mlp_w2, mlp_b2, out_slots, out_attn);
}